// round 1
// baseline (speedup 1.0000x reference)
#include <cuda_runtime.h>
#include <math.h>

#define VOCABC 1400
#define NVEC   350      // float4 per disease row (1400/4)
#define EPSF   1e-6f
#define MAXN   4096     // survival rows

// ---------------- device scratch (no allocations allowed) ----------------
__device__ float g_disease_sum;
__device__ float g_time_sum;
__device__ float g_risk_sum;
__device__ float g_unc_sum;
__device__ float g_conc_sum;
__device__ int   g_disease_cnt;
__device__ int   g_risk_cnt;
__device__ unsigned long long g_pair_cnt;
__device__ float g_m[MAXN];

__global__ void init_kernel() {
    g_disease_sum = 0.f; g_time_sum = 0.f; g_risk_sum = 0.f;
    g_unc_sum = 0.f; g_conc_sum = 0.f;
    g_disease_cnt = 0; g_risk_cnt = 0; g_pair_cnt = 0ull;
}

// ---------------- warp helpers ----------------
__device__ __forceinline__ float warp_sum(float v) {
    #pragma unroll
    for (int o = 16; o > 0; o >>= 1) v += __shfl_xor_sync(0xffffffff, v, o);
    return v;
}
__device__ __forceinline__ float warp_max(float v) {
    #pragma unroll
    for (int o = 16; o > 0; o >>= 1) v = fmaxf(v, __shfl_xor_sync(0xffffffff, v, o));
    return v;
}

// ---------------- survival row means: one warp per row ----------------
__global__ void row_mean_kernel(const float* __restrict__ curves, int n, int T) {
    int w    = (blockIdx.x * blockDim.x + threadIdx.x) >> 5;
    int lane = threadIdx.x & 31;
    if (w >= n) return;
    const float* row = curves + (size_t)w * T;
    float s = 0.f;
    for (int k = lane; k < T; k += 32) s += row[k];
    s = warp_sum(s);
    if (lane == 0) g_m[w] = s / (float)T;
}

// ---------------- disease cross-entropy: one block (128 thr) per row ----------------
__global__ void __launch_bounds__(128) disease_ce_kernel(
        const float* __restrict__ logits, const int* __restrict__ targets) {
    int row = blockIdx.x;
    int t   = threadIdx.x;
    const float4* base = reinterpret_cast<const float4*>(logits) + (size_t)row * NVEC;

    float4 v0 = base[t];                  // t in [0,128) < 350
    float4 v1 = base[t + 128];            // < 350
    bool   h2 = (t + 256) < NVEC;         // t < 94
    float4 v2 = h2 ? base[t + 256]
                   : make_float4(-INFINITY, -INFINITY, -INFINITY, -INFINITY);

    float m = fmaxf(fmaxf(fmaxf(v0.x, v0.y), fmaxf(v0.z, v0.w)),
                    fmaxf(fmaxf(v1.x, v1.y), fmaxf(v1.z, v1.w)));
    m = fmaxf(m, fmaxf(fmaxf(v2.x, v2.y), fmaxf(v2.z, v2.w)));

    __shared__ float sred[4];
    __shared__ float s_tval;

    int tgt = targets[row];
    if (tgt >= 0) {
        int vi = tgt >> 2;
        if ((vi & 127) == t) {
            float4 v = (vi < 128) ? v0 : ((vi < 256) ? v1 : v2);
            int l = tgt & 3;
            s_tval = (l == 0) ? v.x : (l == 1) ? v.y : (l == 2) ? v.z : v.w;
        }
    }

    // block max
    m = warp_max(m);
    int warp = t >> 5;
    if ((t & 31) == 0) sred[warp] = m;
    __syncthreads();
    m = fmaxf(fmaxf(sred[0], sred[1]), fmaxf(sred[2], sred[3]));

    float s = expf(v0.x - m) + expf(v0.y - m) + expf(v0.z - m) + expf(v0.w - m)
            + expf(v1.x - m) + expf(v1.y - m) + expf(v1.z - m) + expf(v1.w - m);
    if (h2)
        s += expf(v2.x - m) + expf(v2.y - m) + expf(v2.z - m) + expf(v2.w - m);

    s = warp_sum(s);
    __syncthreads();                       // protect sred reuse
    if ((t & 31) == 0) sred[warp] = s;
    __syncthreads();

    if (t == 0 && tgt >= 0) {
        float S   = sred[0] + sred[1] + sred[2] + sred[3];
        float nll = -(s_tval - m - logf(S));
        atomicAdd(&g_disease_sum, nll);
        atomicAdd(&g_disease_cnt, 1);
    }
}

// ---------------- time loss + risk CE (C=5) + uncertainty ----------------
__global__ void small_losses_kernel(
        const float* __restrict__ tte, const float* __restrict__ ttgt,
        const float* __restrict__ risk, const int* __restrict__ rtgt,
        const float* __restrict__ unc, int N) {
    int gid    = blockIdx.x * blockDim.x + threadIdx.x;
    int stride = gridDim.x * blockDim.x;
    float tsum = 0.f, rsum = 0.f, usum = 0.f;
    int   rcnt = 0;
    for (int i = gid; i < N; i += stride) {
        float x    = tte[i];
        float rate = 1.0f / (x + EPSF);
        tsum += logf(rate + EPSF) - rate * ttgt[i];
        usum += unc[i];
        int r = rtgt[i];
        if (r >= 0) {
            const float* rl = risk + (size_t)i * 5;
            float a0 = rl[0], a1 = rl[1], a2 = rl[2], a3 = rl[3], a4 = rl[4];
            float mm = fmaxf(fmaxf(fmaxf(a0, a1), fmaxf(a2, a3)), a4);
            float ss = expf(a0 - mm) + expf(a1 - mm) + expf(a2 - mm)
                     + expf(a3 - mm) + expf(a4 - mm);
            float xt = (r == 0) ? a0 : (r == 1) ? a1 : (r == 2) ? a2 : (r == 3) ? a3 : a4;
            rsum += -(xt - mm - logf(ss));
            rcnt++;
        }
    }
    __shared__ float st_[8], sr_[8], su_[8];
    __shared__ int   sc_[8];
    tsum = warp_sum(tsum); rsum = warp_sum(rsum); usum = warp_sum(usum);
    #pragma unroll
    for (int o = 16; o > 0; o >>= 1) rcnt += __shfl_xor_sync(0xffffffff, rcnt, o);
    int warp = threadIdx.x >> 5;
    if ((threadIdx.x & 31) == 0) { st_[warp] = tsum; sr_[warp] = rsum; su_[warp] = usum; sc_[warp] = rcnt; }
    __syncthreads();
    if (threadIdx.x == 0) {
        float T = 0.f, R = 0.f, U = 0.f; int C = 0;
        int nw = blockDim.x >> 5;
        for (int k = 0; k < nw; k++) { T += st_[k]; R += sr_[k]; U += su_[k]; C += sc_[k]; }
        atomicAdd(&g_time_sum, T);
        atomicAdd(&g_risk_sum, R);
        atomicAdd(&g_unc_sum, U);
        atomicAdd(&g_risk_cnt, C);
    }
}

// ---------------- concordance: one block per i, shared-staged t/m ----------------
__global__ void __launch_bounds__(256) concordance_kernel(
        const float* __restrict__ ttimes, const int* __restrict__ events, int n) {
    int i = blockIdx.x;
    if (i >= n) return;
    if (events[i] != 1) return;            // uniform across block: safe early exit

    __shared__ float st[MAXN];
    __shared__ float sm[MAXN];
    for (int k = threadIdx.x; k < n; k += blockDim.x) {
        st[k] = ttimes[k];
        sm[k] = g_m[k];
    }
    __syncthreads();

    float ti = st[i], mi = sm[i];
    float conc = 0.f;
    int   cnt  = 0;
    for (int j = i + 1 + threadIdx.x; j < n; j += blockDim.x) {
        if (ti < st[j]) {
            cnt++;
            float mj = sm[j];
            conc += (mi < mj) ? 1.0f : ((mi == mj) ? 0.5f : 0.0f);
        }
    }
    conc = warp_sum(conc);
    #pragma unroll
    for (int o = 16; o > 0; o >>= 1) cnt += __shfl_xor_sync(0xffffffff, cnt, o);
    __shared__ float sc_[8];
    __shared__ int   si_[8];
    int warp = threadIdx.x >> 5;
    if ((threadIdx.x & 31) == 0) { sc_[warp] = conc; si_[warp] = cnt; }
    __syncthreads();
    if (threadIdx.x == 0) {
        float C = 0.f; int P = 0;
        for (int k = 0; k < 8; k++) { C += sc_[k]; P += si_[k]; }
        if (P > 0) {
            atomicAdd(&g_conc_sum, C);
            atomicAdd(&g_pair_cnt, (unsigned long long)P);
        }
    }
}

// ---------------- finalize ----------------
__global__ void finalize_kernel(float* __restrict__ out, int n_tok) {
    float disease = g_disease_sum / (float)(g_disease_cnt > 0 ? g_disease_cnt : 1);
    float timel   = -g_time_sum / (float)n_tok;
    float risk    = g_risk_sum / (float)(g_risk_cnt > 0 ? g_risk_cnt : 1);
    float surv    = (g_pair_cnt > 0ull)
                      ? 1.0f - g_conc_sum / (float)g_pair_cnt
                      : 0.0f;
    float u       = (g_unc_sum / (float)n_tok) * 0.01f;
    out[0] = disease;
    out[1] = timel;
    out[2] = risk;
    out[3] = surv;
    out[4] = u;
    out[5] = disease + timel + risk + surv + u;
}

// ---------------- launch ----------------
extern "C" void kernel_launch(void* const* d_in, const int* in_sizes, int n_in,
                              void* d_out, int out_size) {
    const float* disease_logits = (const float*)d_in[0];
    const int*   disease_tgt    = (const int*)d_in[1];
    const float* tte            = (const float*)d_in[2];
    const float* ttgt           = (const float*)d_in[3];
    const float* risk           = (const float*)d_in[4];
    const int*   risk_tgt       = (const int*)d_in[5];
    const float* curves         = (const float*)d_in[6];
    const float* surv_tgt       = (const float*)d_in[7];
    const int*   events         = (const int*)d_in[8];
    const float* unc            = (const float*)d_in[9];
    float*       out            = (float*)d_out;

    int n_tok = in_sizes[1];            // 16384
    int n     = in_sizes[7];            // 4096
    int T     = in_sizes[6] / n;        // 120

    init_kernel<<<1, 1>>>();
    row_mean_kernel<<<(n * 32 + 255) / 256, 256>>>(curves, n, T);
    disease_ce_kernel<<<n_tok, 128>>>(disease_logits, disease_tgt);
    small_losses_kernel<<<64, 256>>>(tte, ttgt, risk, risk_tgt, unc, n_tok);
    concordance_kernel<<<n, 256>>>(surv_tgt, events, n);
    finalize_kernel<<<1, 1>>>(out, n_tok);
}

// round 2
// speedup vs baseline: 1.7171x; 1.7171x over previous
#include <cuda_runtime.h>
#include <math.h>

#define VOCABC 1400
#define NVEC   350      // float4 per disease row (1400/4)
#define EPSF   1e-6f
#define MAXN   4096     // survival rows

// slotted accumulators: [metric][slot*32] used; 32-float (128B) stride to put
// each slot on its own L2 line so RED traffic parallelizes across LTS slices.
#define NSLOT  32
#define SSTRIDE 32
// metric ids
#define M_DIS  0
#define M_DCNT 1
#define M_TIME 2
#define M_RISK 3
#define M_RCNT 4
#define M_UNC  5
#define M_CONC 6
#define M_PAIR 7
#define NMET   8

__device__ float g_acc[NMET][NSLOT * SSTRIDE];
__device__ float g_m[MAXN];

__device__ __forceinline__ void slot_add(int metric, int slot, float v) {
    atomicAdd(&g_acc[metric][slot * SSTRIDE], v);
}

// ---------------- warp helpers ----------------
__device__ __forceinline__ float warp_sum(float v) {
    #pragma unroll
    for (int o = 16; o > 0; o >>= 1) v += __shfl_xor_sync(0xffffffff, v, o);
    return v;
}
__device__ __forceinline__ float warp_max(float v) {
    #pragma unroll
    for (int o = 16; o > 0; o >>= 1) v = fmaxf(v, __shfl_xor_sync(0xffffffff, v, o));
    return v;
}

// ---------------- survival row means (one warp per row) + accumulator init ----
__global__ void row_mean_kernel(const float* __restrict__ curves, int n, int T) {
    // block 0 zeroes the slot accumulators (no other kernel touches them yet;
    // later kernels are stream-ordered after this one)
    if (blockIdx.x == 0 && threadIdx.x < NMET * NSLOT) {
        int m = threadIdx.x / NSLOT, s = threadIdx.x % NSLOT;
        g_acc[m][s * SSTRIDE] = 0.f;
    }
    int w    = (blockIdx.x * blockDim.x + threadIdx.x) >> 5;
    int lane = threadIdx.x & 31;
    if (w >= n) return;
    const float* row = curves + (size_t)w * T;
    float s = 0.f;
    for (int k = lane; k < T; k += 32) s += row[k];
    s = warp_sum(s);
    if (lane == 0) g_m[w] = s / (float)T;
}

// ---------------- disease CE (block/row) + fused per-token small losses ------
__global__ void __launch_bounds__(128) disease_ce_kernel(
        const float* __restrict__ logits, const int* __restrict__ targets,
        const float* __restrict__ tte, const float* __restrict__ ttgt,
        const float* __restrict__ risk, const int* __restrict__ rtgt,
        const float* __restrict__ unc) {
    int row  = blockIdx.x;
    int t    = threadIdx.x;
    int slot = row & (NSLOT - 1);
    const float4* base = reinterpret_cast<const float4*>(logits) + (size_t)row * NVEC;

    float4 v0 = base[t];                  // t in [0,128) < 350
    float4 v1 = base[t + 128];            // < 350
    bool   h2 = (t + 256) < NVEC;         // t < 94
    float4 v2 = h2 ? base[t + 256]
                   : make_float4(-INFINITY, -INFINITY, -INFINITY, -INFINITY);

    // ---- fused per-token scalar losses (idle-lane work, overlaps reduction) ----
    if (t == 32) {
        float x    = tte[row];
        float rate = 1.0f / (x + EPSF);
        float tl   = __logf(rate + EPSF) - rate * ttgt[row];
        slot_add(M_TIME, slot, tl);
        slot_add(M_UNC,  slot, unc[row]);
    } else if (t == 64) {
        int r = rtgt[row];
        if (r >= 0) {
            const float* rl = risk + (size_t)row * 5;
            float a0 = rl[0], a1 = rl[1], a2 = rl[2], a3 = rl[3], a4 = rl[4];
            float mm = fmaxf(fmaxf(fmaxf(a0, a1), fmaxf(a2, a3)), a4);
            float ss = __expf(a0 - mm) + __expf(a1 - mm) + __expf(a2 - mm)
                     + __expf(a3 - mm) + __expf(a4 - mm);
            float xt = (r == 0) ? a0 : (r == 1) ? a1 : (r == 2) ? a2 : (r == 3) ? a3 : a4;
            slot_add(M_RISK, slot, -(xt - mm - __logf(ss)));
            slot_add(M_RCNT, slot, 1.0f);
        }
    }

    float m = fmaxf(fmaxf(fmaxf(v0.x, v0.y), fmaxf(v0.z, v0.w)),
                    fmaxf(fmaxf(v1.x, v1.y), fmaxf(v1.z, v1.w)));
    m = fmaxf(m, fmaxf(fmaxf(v2.x, v2.y), fmaxf(v2.z, v2.w)));

    __shared__ float sred[4];
    __shared__ float s_tval;

    int tgt = targets[row];
    if (tgt >= 0) {
        int vi = tgt >> 2;
        if ((vi & 127) == t) {
            float4 v = (vi < 128) ? v0 : ((vi < 256) ? v1 : v2);
            int l = tgt & 3;
            s_tval = (l == 0) ? v.x : (l == 1) ? v.y : (l == 2) ? v.z : v.w;
        }
    }

    // block max
    m = warp_max(m);
    int warp = t >> 5;
    if ((t & 31) == 0) sred[warp] = m;
    __syncthreads();
    m = fmaxf(fmaxf(sred[0], sred[1]), fmaxf(sred[2], sred[3]));

    float s = __expf(v0.x - m) + __expf(v0.y - m) + __expf(v0.z - m) + __expf(v0.w - m)
            + __expf(v1.x - m) + __expf(v1.y - m) + __expf(v1.z - m) + __expf(v1.w - m);
    if (h2)
        s += __expf(v2.x - m) + __expf(v2.y - m) + __expf(v2.z - m) + __expf(v2.w - m);

    s = warp_sum(s);
    __syncthreads();                       // protect sred reuse
    if ((t & 31) == 0) sred[warp] = s;
    __syncthreads();

    if (t == 0 && tgt >= 0) {
        float S   = sred[0] + sred[1] + sred[2] + sred[3];
        float nll = -(s_tval - m - __logf(S));
        slot_add(M_DIS,  slot, nll);
        slot_add(M_DCNT, slot, 1.0f);
    }
}

// ---------------- concordance: persistent blocks, smem staged once ----------
#define CONC_BLOCKS 296
__global__ void __launch_bounds__(256) concordance_kernel(
        const float* __restrict__ ttimes, const int* __restrict__ events, int n) {
    __shared__ float st[MAXN];
    __shared__ float sm[MAXN];
    __shared__ int   se[MAXN];
    int tid = threadIdx.x;
    for (int k = tid; k < n; k += 256) {
        st[k] = ttimes[k];
        sm[k] = g_m[k];
        se[k] = events[k];
    }
    __syncthreads();

    float conc = 0.f;
    float cnt  = 0.f;
    for (int i = blockIdx.x; i < n; i += gridDim.x) {
        if (se[i] != 1) continue;
        float ti = st[i], mi = sm[i];
        for (int j = i + 1 + tid; j < n; j += 256) {
            float tj = st[j];
            if (ti < tj) {
                cnt += 1.0f;
                float mj = sm[j];
                conc += (mi < mj) ? 1.0f : ((mi == mj) ? 0.5f : 0.0f);
            }
        }
    }

    conc = warp_sum(conc);
    cnt  = warp_sum(cnt);
    __shared__ float sc_[8], si_[8];
    int warp = tid >> 5;
    if ((tid & 31) == 0) { sc_[warp] = conc; si_[warp] = cnt; }
    __syncthreads();
    if (tid == 0) {
        float C = 0.f, P = 0.f;
        #pragma unroll
        for (int k = 0; k < 8; k++) { C += sc_[k]; P += si_[k]; }
        int slot = blockIdx.x & (NSLOT - 1);
        slot_add(M_CONC, slot, C);
        slot_add(M_PAIR, slot, P);
    }
}

// ---------------- finalize ----------------
__global__ void finalize_kernel(float* __restrict__ out, int n_tok) {
    __shared__ float tot[NMET];
    if (threadIdx.x < NMET) {
        float s = 0.f;
        #pragma unroll
        for (int k = 0; k < NSLOT; k++) s += g_acc[threadIdx.x][k * SSTRIDE];
        tot[threadIdx.x] = s;
    }
    __syncthreads();
    if (threadIdx.x == 0) {
        float dcnt    = tot[M_DCNT] > 0.f ? tot[M_DCNT] : 1.f;
        float rcnt    = tot[M_RCNT] > 0.f ? tot[M_RCNT] : 1.f;
        float disease = tot[M_DIS] / dcnt;
        float timel   = -tot[M_TIME] / (float)n_tok;
        float riskl   = tot[M_RISK] / rcnt;
        float surv    = (tot[M_PAIR] > 0.f) ? 1.0f - tot[M_CONC] / tot[M_PAIR] : 0.0f;
        float u       = (tot[M_UNC] / (float)n_tok) * 0.01f;
        out[0] = disease;
        out[1] = timel;
        out[2] = riskl;
        out[3] = surv;
        out[4] = u;
        out[5] = disease + timel + riskl + surv + u;
    }
}

// ---------------- launch ----------------
extern "C" void kernel_launch(void* const* d_in, const int* in_sizes, int n_in,
                              void* d_out, int out_size) {
    const float* disease_logits = (const float*)d_in[0];
    const int*   disease_tgt    = (const int*)d_in[1];
    const float* tte            = (const float*)d_in[2];
    const float* ttgt           = (const float*)d_in[3];
    const float* risk           = (const float*)d_in[4];
    const int*   risk_tgt       = (const int*)d_in[5];
    const float* curves         = (const float*)d_in[6];
    const float* surv_tgt       = (const float*)d_in[7];
    const int*   events         = (const int*)d_in[8];
    const float* unc            = (const float*)d_in[9];
    float*       out            = (float*)d_out;

    int n_tok = in_sizes[1];            // 16384
    int n     = in_sizes[7];            // 4096
    int T     = in_sizes[6] / n;        // 120

    row_mean_kernel<<<(n * 32 + 255) / 256, 256>>>(curves, n, T);
    disease_ce_kernel<<<n_tok, 128>>>(disease_logits, disease_tgt,
                                      tte, ttgt, risk, risk_tgt, unc);
    concordance_kernel<<<CONC_BLOCKS, 256>>>(surv_tgt, events, n);
    finalize_kernel<<<1, 32>>>(out, n_tok);
}

// round 3
// speedup vs baseline: 1.8596x; 1.0830x over previous
#include <cuda_runtime.h>
#include <math.h>

#define VOCABC 1400
#define NVEC   350      // float4 per disease row (1400/4)
#define EPSF   1e-6f
#define MAXN   4096     // survival rows

// slotted accumulators: 128B stride -> each slot on its own L2 line
#define NSLOT  32
#define SSTRIDE 32
#define M_DIS  0
#define M_DCNT 1
#define M_TIME 2
#define M_RISK 3
#define M_RCNT 4
#define M_UNC  5
#define M_CONC 6
#define M_PAIR 7
#define NMET   8

// zero-initialized at module load; finalizing block resets them after reading,
// so every kernel_launch execution (correctness run + every graph replay)
// starts from zeros. No init kernel needed.
__device__ float        g_acc[NMET][NSLOT * SSTRIDE];
__device__ float        g_m[MAXN];
__device__ unsigned int g_done;

__device__ __forceinline__ void slot_add(int metric, int slot, float v) {
    atomicAdd(&g_acc[metric][slot * SSTRIDE], v);
}

__device__ __forceinline__ float warp_sum(float v) {
    #pragma unroll
    for (int o = 16; o > 0; o >>= 1) v += __shfl_xor_sync(0xffffffff, v, o);
    return v;
}
__device__ __forceinline__ float warp_max(float v) {
    #pragma unroll
    for (int o = 16; o > 0; o >>= 1) v = fmaxf(v, __shfl_xor_sync(0xffffffff, v, o));
    return v;
}

// ---------------- kernel 1: disease CE + row means + small per-token losses --
__global__ void __launch_bounds__(128) disease_ce_kernel(
        const float* __restrict__ logits, const int* __restrict__ targets,
        const float* __restrict__ tte, const float* __restrict__ ttgt,
        const float* __restrict__ risk, const int* __restrict__ rtgt,
        const float* __restrict__ unc,
        const float* __restrict__ curves, int n_surv, int T) {
    int row  = blockIdx.x;
    int t    = threadIdx.x;
    int slot = row & (NSLOT - 1);
    const float4* base = reinterpret_cast<const float4*>(logits) + (size_t)row * NVEC;

    float4 v0 = base[t];                  // t in [0,128) < 350
    float4 v1 = base[t + 128];            // < 350
    bool   h2 = (t + 256) < NVEC;         // t < 94
    float4 v2 = h2 ? base[t + 256]
                   : make_float4(-INFINITY, -INFINITY, -INFINITY, -INFINITY);

    // ---- fused survival row mean: warp 1 (t in [32,64)) handles row < n_surv
    if (row < n_surv && t >= 32 && t < 64) {
        int lane = t - 32;
        const float* crow = curves + (size_t)row * T;
        float s = 0.f;
        for (int k = lane; k < T; k += 32) s += crow[k];
        #pragma unroll
        for (int o = 16; o > 0; o >>= 1) s += __shfl_xor_sync(0xffffffff, s, o, 32);
        if (lane == 0) g_m[row] = s / (float)T;
    }

    // ---- fused per-token scalar losses (idle-lane work) ----
    if (t == 96) {
        float x    = tte[row];
        float rate = 1.0f / (x + EPSF);
        float tl   = __logf(rate + EPSF) - rate * ttgt[row];
        slot_add(M_TIME, slot, tl);
        slot_add(M_UNC,  slot, unc[row]);
    } else if (t == 64) {
        int r = rtgt[row];
        if (r >= 0) {
            const float* rl = risk + (size_t)row * 5;
            float a0 = rl[0], a1 = rl[1], a2 = rl[2], a3 = rl[3], a4 = rl[4];
            float mm = fmaxf(fmaxf(fmaxf(a0, a1), fmaxf(a2, a3)), a4);
            float ss = __expf(a0 - mm) + __expf(a1 - mm) + __expf(a2 - mm)
                     + __expf(a3 - mm) + __expf(a4 - mm);
            float xt = (r == 0) ? a0 : (r == 1) ? a1 : (r == 2) ? a2 : (r == 3) ? a3 : a4;
            slot_add(M_RISK, slot, -(xt - mm - __logf(ss)));
            slot_add(M_RCNT, slot, 1.0f);
        }
    }

    float m = fmaxf(fmaxf(fmaxf(v0.x, v0.y), fmaxf(v0.z, v0.w)),
                    fmaxf(fmaxf(v1.x, v1.y), fmaxf(v1.z, v1.w)));
    m = fmaxf(m, fmaxf(fmaxf(v2.x, v2.y), fmaxf(v2.z, v2.w)));

    __shared__ float sred[4];
    __shared__ float s_tval;

    int tgt = targets[row];
    if (tgt >= 0) {
        int vi = tgt >> 2;
        if ((vi & 127) == t) {
            float4 v = (vi < 128) ? v0 : ((vi < 256) ? v1 : v2);
            int l = tgt & 3;
            s_tval = (l == 0) ? v.x : (l == 1) ? v.y : (l == 2) ? v.z : v.w;
        }
    }

    m = warp_max(m);
    int warp = t >> 5;
    if ((t & 31) == 0) sred[warp] = m;
    __syncthreads();
    m = fmaxf(fmaxf(sred[0], sred[1]), fmaxf(sred[2], sred[3]));

    float s = __expf(v0.x - m) + __expf(v0.y - m) + __expf(v0.z - m) + __expf(v0.w - m)
            + __expf(v1.x - m) + __expf(v1.y - m) + __expf(v1.z - m) + __expf(v1.w - m);
    if (h2)
        s += __expf(v2.x - m) + __expf(v2.y - m) + __expf(v2.z - m) + __expf(v2.w - m);

    s = warp_sum(s);
    __syncthreads();
    if ((t & 31) == 0) sred[warp] = s;
    __syncthreads();

    if (t == 0 && tgt >= 0) {
        float S   = sred[0] + sred[1] + sred[2] + sred[3];
        float nll = -(s_tval - m - __logf(S));
        slot_add(M_DIS,  slot, nll);
        slot_add(M_DCNT, slot, 1.0f);
    }
}

// ---------------- kernel 2: concordance (persistent) + fused finalize -------
#define CONC_BLOCKS 296
__global__ void __launch_bounds__(256) concordance_kernel(
        const float* __restrict__ ttimes, const int* __restrict__ events,
        int n, float* __restrict__ out, int n_tok) {
    __shared__ float2 stm[MAXN];           // (time, mean) packed -> 1 LDS.64 per j
    int tid = threadIdx.x;
    for (int k = tid; k < n; k += 256)
        stm[k] = make_float2(ttimes[k], g_m[k]);
    __syncthreads();

    float conc = 0.f;
    float cnt  = 0.f;
    for (int i = blockIdx.x; i < n; i += gridDim.x) {
        if (events[i] != 1) continue;
        float2 im = stm[i];
        float ti = im.x, mi = im.y;
        for (int j = i + 1 + tid; j < n; j += 256) {
            float2 jm = stm[j];
            if (ti < jm.x) {
                cnt += 1.0f;
                conc += (mi < jm.y) ? 1.0f : ((mi == jm.y) ? 0.5f : 0.0f);
            }
        }
    }

    conc = warp_sum(conc);
    cnt  = warp_sum(cnt);
    __shared__ float sc_[8], si_[8];
    int warp = tid >> 5;
    if ((tid & 31) == 0) { sc_[warp] = conc; si_[warp] = cnt; }
    __syncthreads();
    if (tid == 0) {
        float C = 0.f, P = 0.f;
        #pragma unroll
        for (int k = 0; k < 8; k++) { C += sc_[k]; P += si_[k]; }
        int slot = blockIdx.x & (NSLOT - 1);
        slot_add(M_CONC, slot, C);
        slot_add(M_PAIR, slot, P);
    }

    // ---- last-done block finalizes and resets ----
    __shared__ bool amLast;
    if (tid == 0) {
        __threadfence();
        unsigned v = atomicAdd(&g_done, 1u);
        amLast = (v == gridDim.x - 1);
    }
    __syncthreads();
    if (!amLast) return;

    __shared__ float tot[NMET];
    if (tid < NMET) {
        float s = 0.f;
        #pragma unroll
        for (int k = 0; k < NSLOT; k++) s += g_acc[tid][k * SSTRIDE];
        tot[tid] = s;
    }
    __syncthreads();
    if (tid == 0) {
        float dcnt    = tot[M_DCNT] > 0.f ? tot[M_DCNT] : 1.f;
        float rcnt    = tot[M_RCNT] > 0.f ? tot[M_RCNT] : 1.f;
        float disease = tot[M_DIS] / dcnt;
        float timel   = -tot[M_TIME] / (float)n_tok;
        float riskl   = tot[M_RISK] / rcnt;
        float surv    = (tot[M_PAIR] > 0.f) ? 1.0f - tot[M_CONC] / tot[M_PAIR] : 0.0f;
        float u       = (tot[M_UNC] / (float)n_tok) * 0.01f;
        out[0] = disease;
        out[1] = timel;
        out[2] = riskl;
        out[3] = surv;
        out[4] = u;
        out[5] = disease + timel + riskl + surv + u;
        g_done = 0u;
    }
    // reset accumulators for the next execution (256 threads, 256 entries)
    {
        int mtr = tid / NSLOT, s = tid % NSLOT;
        if (mtr < NMET) g_acc[mtr][s * SSTRIDE] = 0.f;
    }
}

// ---------------- launch ----------------
extern "C" void kernel_launch(void* const* d_in, const int* in_sizes, int n_in,
                              void* d_out, int out_size) {
    const float* disease_logits = (const float*)d_in[0];
    const int*   disease_tgt    = (const int*)d_in[1];
    const float* tte            = (const float*)d_in[2];
    const float* ttgt           = (const float*)d_in[3];
    const float* risk           = (const float*)d_in[4];
    const int*   risk_tgt       = (const int*)d_in[5];
    const float* curves         = (const float*)d_in[6];
    const float* surv_tgt       = (const float*)d_in[7];
    const int*   events         = (const int*)d_in[8];
    const float* unc            = (const float*)d_in[9];
    float*       out            = (float*)d_out;

    int n_tok = in_sizes[1];            // 16384
    int n     = in_sizes[7];            // 4096
    int T     = in_sizes[6] / n;        // 120

    disease_ce_kernel<<<n_tok, 128>>>(disease_logits, disease_tgt,
                                      tte, ttgt, risk, risk_tgt, unc,
                                      curves, n, T);
    concordance_kernel<<<CONC_BLOCKS, 256>>>(surv_tgt, events, n, out, n_tok);
}